// round 1
// baseline (speedup 1.0000x reference)
#include <cuda_runtime.h>

// Encoding layer: B=64, C=512, N=784 (28x28), K=32
// x layout: (B, C, N)  -> descriptor x_n is strided (stride N in c)
// out: (B, K, C) fp32

#define CDIM 512
#define KDIM 32
#define NPIX 784
#define BDIM 64
#define CHUNKS 9
#define TS 16
#define TILES_PER_B 49   // 784 / 16
#define XSTRIDE 516      // 512 + 4 pad: keeps 16B alignment, breaks bank conflicts

// Scratch partials: fully written by kernel1 every launch, reduced by kernel2.
__device__ float g_wx[(size_t)BDIM * CHUNKS * KDIM * CDIM];   // 37.7 MB
__device__ float g_wsum[BDIM * CHUNKS * KDIM];

__global__ __launch_bounds__(256, 1)
void enc_main_kernel(const float* __restrict__ x,
                     const float* __restrict__ cw,
                     const float* __restrict__ scale) {
    const int b     = blockIdx.x / CHUNKS;
    const int chunk = blockIdx.x % CHUNKS;
    const int tile0 = (chunk * TILES_PER_B) / CHUNKS;
    const int tile1 = ((chunk + 1) * TILES_PER_B) / CHUNKS;
    const int t = threadIdx.x;
    const int w = t >> 5;     // warp 0..7 -> owns k in [4w, 4w+4)
    const int l = t & 31;     // lane -> owns c = l + 32*j, j=0..15

    __shared__ float x_s[TS * XSTRIDE];
    __shared__ float xc_s[TS * KDIM];
    __shared__ float a_s[TS * KDIM];
    __shared__ float xsq_s[TS];
    __shared__ float csq_s[KDIM];
    __shared__ float scl_s[KDIM];
    __shared__ float wsum_s[8][KDIM];

    // ---- codewords resident in registers: cw_r[kk][j] = cw[4w+kk][l+32j]
    float cw_r[4][16];
#pragma unroll
    for (int kk = 0; kk < 4; kk++)
#pragma unroll
        for (int j = 0; j < 16; j++)
            cw_r[kk][j] = __ldg(&cw[(4 * w + kk) * CDIM + l + 32 * j]);

    // ---- c_sq per k (warp butterfly reduce), scale into smem
#pragma unroll
    for (int kk = 0; kk < 4; kk++) {
        float s = 0.f;
#pragma unroll
        for (int j = 0; j < 16; j++) s = fmaf(cw_r[kk][j], cw_r[kk][j], s);
#pragma unroll
        for (int o = 16; o; o >>= 1) s += __shfl_xor_sync(0xffffffffu, s, o);
        if (l == 0) csq_s[4 * w + kk] = s;
    }
    if (t < KDIM) scl_s[t] = __ldg(&scale[t]);

    float acc[4][16];
#pragma unroll
    for (int kk = 0; kk < 4; kk++)
#pragma unroll
        for (int j = 0; j < 16; j++) acc[kk][j] = 0.f;
    float wsum_acc = 0.f;   // lane l accumulates A-sum for k=l (softmax phase)

    const float* xb = x + (size_t)b * CDIM * NPIX;
    const int nl = t & 15;   // row loaded by this thread
    const int cb = t >> 4;   // c base for loads

    for (int tile = tile0; tile < tile1; tile++) {
        const int n0 = tile * TS;
        __syncthreads();                       // x_s / a_s reuse fence
        if (t < TS) xsq_s[t] = 0.f;
        __syncthreads();

        // ---- stage x tile (coalesced LDG: 16 consecutive n per c) + xsq partial
        float xsqp = 0.f;
#pragma unroll
        for (int i = 0; i < 32; i++) {
            int c = cb + 16 * i;
            float v = __ldg(&xb[c * NPIX + n0 + nl]);
            x_s[nl * XSTRIDE + c] = v;
            xsqp = fmaf(v, v, xsqp);
        }
        atomicAdd(&xsq_s[nl], xsqp);
        __syncthreads();

        // ---- phase 1: xc[n][k] dots (x from smem conflict-free, cw from regs)
        for (int n = 0; n < TS; n++) {
            float s0 = 0.f, s1 = 0.f, s2 = 0.f, s3 = 0.f;
#pragma unroll
            for (int j = 0; j < 16; j++) {
                float xv = x_s[n * XSTRIDE + l + 32 * j];
                s0 = fmaf(xv, cw_r[0][j], s0);
                s1 = fmaf(xv, cw_r[1][j], s1);
                s2 = fmaf(xv, cw_r[2][j], s2);
                s3 = fmaf(xv, cw_r[3][j], s3);
            }
#pragma unroll
            for (int o = 16; o; o >>= 1) {
                s0 += __shfl_xor_sync(0xffffffffu, s0, o);
                s1 += __shfl_xor_sync(0xffffffffu, s1, o);
                s2 += __shfl_xor_sync(0xffffffffu, s2, o);
                s3 += __shfl_xor_sync(0xffffffffu, s3, o);
            }
            if (l == 0)
                *(float4*)&xc_s[n * KDIM + 4 * w] = make_float4(s0, s1, s2, s3);
        }
        __syncthreads();

        // ---- softmax over k: warp w handles rows w and w+8; lane = k
#pragma unroll
        for (int r = 0; r < 2; r++) {
            int n = w + 8 * r;
            float xc = xc_s[n * KDIM + l];
            float d = scl_s[l] * (xsq_s[n] - 2.f * xc + csq_s[l]);
            float m = d;
#pragma unroll
            for (int o = 16; o; o >>= 1) m = fmaxf(m, __shfl_xor_sync(0xffffffffu, m, o));
            float e = __expf(d - m);
            float ssum = e;
#pragma unroll
            for (int o = 16; o; o >>= 1) ssum += __shfl_xor_sync(0xffffffffu, ssum, o);
            float a = __fdividef(e, ssum);
            a_s[n * KDIM + l] = a;
            wsum_acc += a;
        }
        __syncthreads();

        // ---- phase 2: wx[k][c] += A[n][k] * x[n][c] into registers
        for (int n = 0; n < TS; n++) {
            float4 av = *(const float4*)&a_s[n * KDIM + 4 * w];  // broadcast
#pragma unroll
            for (int j = 0; j < 16; j++) {
                float xv = x_s[n * XSTRIDE + l + 32 * j];
                acc[0][j] = fmaf(av.x, xv, acc[0][j]);
                acc[1][j] = fmaf(av.y, xv, acc[1][j]);
                acc[2][j] = fmaf(av.z, xv, acc[2][j]);
                acc[3][j] = fmaf(av.w, xv, acc[3][j]);
            }
        }
    }

    // ---- write per-chunk partials (coalesced)
    float* wxp = g_wx + (size_t)(b * CHUNKS + chunk) * KDIM * CDIM;
#pragma unroll
    for (int kk = 0; kk < 4; kk++)
#pragma unroll
        for (int j = 0; j < 16; j++)
            wxp[(4 * w + kk) * CDIM + l + 32 * j] = acc[kk][j];

    wsum_s[w][l] = wsum_acc;
    __syncthreads();
    if (t < KDIM) {
        float s = 0.f;
#pragma unroll
        for (int ww = 0; ww < 8; ww++) s += wsum_s[ww][t];
        g_wsum[(b * CHUNKS + chunk) * KDIM + t] = s;
    }
}

__global__ void enc_epilogue_kernel(const float* __restrict__ cw,
                                    float* __restrict__ out) {
    int idx = blockIdx.x * blockDim.x + threadIdx.x;  // over B*K*C
    int c = idx & (CDIM - 1);
    int k = (idx >> 9) & (KDIM - 1);
    int b = idx >> 14;
    float s = 0.f, ws = 0.f;
#pragma unroll
    for (int ch = 0; ch < CHUNKS; ch++) {
        s  += g_wx[(size_t)(b * CHUNKS + ch) * KDIM * CDIM + k * CDIM + c];
        ws += g_wsum[(b * CHUNKS + ch) * KDIM + k];
    }
    out[idx] = s - ws * __ldg(&cw[k * CDIM + c]);
}

extern "C" void kernel_launch(void* const* d_in, const int* in_sizes, int n_in,
                              void* d_out, int out_size) {
    const float* x     = (const float*)d_in[0];
    const float* cw    = (const float*)d_in[1];
    const float* scale = (const float*)d_in[2];
    float* out = (float*)d_out;

    enc_main_kernel<<<BDIM * CHUNKS, 256>>>(x, cw, scale);
    enc_epilogue_kernel<<<(BDIM * KDIM * CDIM) / 256, 256>>>(cw, out);
}

// round 2
// speedup vs baseline: 1.1985x; 1.1985x over previous
#include <cuda_runtime.h>

// Encoding layer: B=64, C=512, N=784 (28x28), K=32
// x layout: (B, C, N); out: (B, K, C) fp32

#define CDIM 512
#define KDIM 32
#define NPIX 784
#define BDIM 64
#define CHUNKS 9
#define TS 16
#define TILES_PER_B 49
#define XSTRIDE 516      // 512 + 4 pad: 8B-aligned rows, conflict-free LDS.64

typedef unsigned long long u64;

__device__ float g_wx[(size_t)BDIM * CHUNKS * KDIM * CDIM];
__device__ float g_wsum[BDIM * CHUNKS * KDIM];

__device__ __forceinline__ u64 pack2(float lo, float hi) {
    u64 r; asm("mov.b64 %0, {%1,%2};" : "=l"(r) : "f"(lo), "f"(hi)); return r;
}
__device__ __forceinline__ float2 unpack2(u64 v) {
    float2 r; asm("mov.b64 {%0,%1}, %2;" : "=f"(r.x), "=f"(r.y) : "l"(v)); return r;
}
#define FMA2(d, a, b, c) \
    asm("fma.rn.f32x2 %0, %1, %2, %3;" : "=l"(d) : "l"(a), "l"(b), "l"(c))

__global__ __launch_bounds__(256, 1)
void enc_main_kernel(const float* __restrict__ x,
                     const float* __restrict__ cw,
                     const float* __restrict__ scale) {
    const int b     = blockIdx.x / CHUNKS;
    const int chunk = blockIdx.x % CHUNKS;
    const int tile0 = (chunk * TILES_PER_B) / CHUNKS;
    const int tile1 = ((chunk + 1) * TILES_PER_B) / CHUNKS;
    const int t = threadIdx.x;
    const int w = t >> 5;     // warp 0..7 -> owns k in [4w, 4w+4)
    const int l = t & 31;     // lane -> owns c pairs (2l+64j, 2l+1+64j), j=0..7

    __shared__ float x_s[TS * XSTRIDE];
    __shared__ float xc_s[TS * KDIM];
    __shared__ float a_s[TS * KDIM];
    __shared__ float csq_s[KDIM];
    __shared__ float scl_s[KDIM];
    __shared__ float wsum_s[8][KDIM];

    // ---- codewords resident in registers, packed f32x2: cw2[kk][j] = cw[4w+kk][2l+64j .. +1]
    u64 cw2[4][8];
#pragma unroll
    for (int kk = 0; kk < 4; kk++) {
        const float2* cwp = (const float2*)(cw + (4 * w + kk) * CDIM);
#pragma unroll
        for (int j = 0; j < 8; j++) {
            float2 v = __ldg(&cwp[l + 32 * j]);
            cw2[kk][j] = pack2(v.x, v.y);
        }
    }

    // ---- c_sq per k (warp butterfly), scale into smem
#pragma unroll
    for (int kk = 0; kk < 4; kk++) {
        float s = 0.f;
#pragma unroll
        for (int j = 0; j < 8; j++) {
            float2 v = unpack2(cw2[kk][j]);
            s = fmaf(v.x, v.x, fmaf(v.y, v.y, s));
        }
#pragma unroll
        for (int o = 16; o; o >>= 1) s += __shfl_xor_sync(0xffffffffu, s, o);
        if (l == 0) csq_s[4 * w + kk] = s;
    }
    if (t < KDIM) scl_s[t] = __ldg(&scale[t]);

    u64 acc2[4][8];
#pragma unroll
    for (int kk = 0; kk < 4; kk++)
#pragma unroll
        for (int j = 0; j < 8; j++) acc2[kk][j] = 0ull;
    float wsum_acc = 0.f;

    const float* xb = x + (size_t)b * CDIM * NPIX;
    const int nl = t & 15;   // row loaded by this thread
    const int cb = t >> 4;   // c base for staging loads

    for (int tile = tile0; tile < tile1; tile++) {
        const int n0 = tile * TS;
        __syncthreads();                       // x_s / a_s reuse fence

        // ---- stage x tile (coalesced: warp covers 2 c-rows x 16 n = 128B/LDG)
#pragma unroll
        for (int i = 0; i < 32; i++) {
            int c = cb + 16 * i;
            x_s[nl * XSTRIDE + c] = __ldg(&xb[c * NPIX + n0 + nl]);
        }
        __syncthreads();

        // ---- phase 1: xc[n][k] dots, packed f32x2, rows in pairs for shfl ILP
        for (int np = 0; np < TS; np += 2) {
            u64 s2[2][4];
#pragma unroll
            for (int r = 0; r < 2; r++) {
                const u64* xrow = (const u64*)(x_s + (np + r) * XSTRIDE);
                u64 a0 = 0ull, a1 = 0ull, a2 = 0ull, a3 = 0ull;
#pragma unroll
                for (int j = 0; j < 8; j++) {
                    u64 xv = xrow[l + 32 * j];
                    FMA2(a0, xv, cw2[0][j], a0);
                    FMA2(a1, xv, cw2[1][j], a1);
                    FMA2(a2, xv, cw2[2][j], a2);
                    FMA2(a3, xv, cw2[3][j], a3);
                }
                s2[r][0] = a0; s2[r][1] = a1; s2[r][2] = a2; s2[r][3] = a3;
            }
            float v[2][4];
#pragma unroll
            for (int r = 0; r < 2; r++)
#pragma unroll
                for (int kk = 0; kk < 4; kk++) {
                    float2 p = unpack2(s2[r][kk]);
                    v[r][kk] = p.x + p.y;
                }
#pragma unroll
            for (int o = 16; o; o >>= 1)
#pragma unroll
                for (int r = 0; r < 2; r++)
#pragma unroll
                    for (int kk = 0; kk < 4; kk++)
                        v[r][kk] += __shfl_xor_sync(0xffffffffu, v[r][kk], o);
            if (l == 0) {
                *(float4*)&xc_s[(np + 0) * KDIM + 4 * w] =
                    make_float4(v[0][0], v[0][1], v[0][2], v[0][3]);
                *(float4*)&xc_s[(np + 1) * KDIM + 4 * w] =
                    make_float4(v[1][0], v[1][1], v[1][2], v[1][3]);
            }
        }
        __syncthreads();

        // ---- softmax: warp w handles rows w and w+8; lane = k; xsq computed inline
#pragma unroll
        for (int r = 0; r < 2; r++) {
            int n = w + 8 * r;
            float xs = 0.f;
#pragma unroll
            for (int j = 0; j < 16; j++) {
                float xv = x_s[n * XSTRIDE + l + 32 * j];
                xs = fmaf(xv, xv, xs);
            }
#pragma unroll
            for (int o = 16; o; o >>= 1) xs += __shfl_xor_sync(0xffffffffu, xs, o);

            float xc = xc_s[n * KDIM + l];
            float d = scl_s[l] * (xs - 2.f * xc + csq_s[l]);
            float m = d;
#pragma unroll
            for (int o = 16; o; o >>= 1) m = fmaxf(m, __shfl_xor_sync(0xffffffffu, m, o));
            float e = __expf(d - m);
            float ssum = e;
#pragma unroll
            for (int o = 16; o; o >>= 1) ssum += __shfl_xor_sync(0xffffffffu, ssum, o);
            float a = __fdividef(e, ssum);
            a_s[n * KDIM + l] = a;
            wsum_acc += a;
        }
        __syncthreads();

        // ---- phase 2: wx[k][c] += A[n][k] * x[n][c], packed f32x2
        for (int n = 0; n < TS; n++) {
            float4 av = *(const float4*)&a_s[n * KDIM + 4 * w];  // broadcast
            u64 p0 = pack2(av.x, av.x);
            u64 p1 = pack2(av.y, av.y);
            u64 p2 = pack2(av.z, av.z);
            u64 p3 = pack2(av.w, av.w);
            const u64* xrow = (const u64*)(x_s + n * XSTRIDE);
#pragma unroll
            for (int j = 0; j < 8; j++) {
                u64 xv = xrow[l + 32 * j];
                FMA2(acc2[0][j], p0, xv, acc2[0][j]);
                FMA2(acc2[1][j], p1, xv, acc2[1][j]);
                FMA2(acc2[2][j], p2, xv, acc2[2][j]);
                FMA2(acc2[3][j], p3, xv, acc2[3][j]);
            }
        }
    }

    // ---- write per-chunk partials (float2, coalesced)
    float* wxp = g_wx + (size_t)(b * CHUNKS + chunk) * KDIM * CDIM;
#pragma unroll
    for (int kk = 0; kk < 4; kk++)
#pragma unroll
        for (int j = 0; j < 8; j++) {
            float2 p = unpack2(acc2[kk][j]);
            *(float2*)&wxp[(4 * w + kk) * CDIM + 2 * l + 64 * j] = p;
        }

    wsum_s[w][l] = wsum_acc;
    __syncthreads();
    if (t < KDIM) {
        float s = 0.f;
#pragma unroll
        for (int ww = 0; ww < 8; ww++) s += wsum_s[ww][t];
        g_wsum[(b * CHUNKS + chunk) * KDIM + t] = s;
    }
}

__global__ void enc_epilogue_kernel(const float* __restrict__ cw,
                                    float* __restrict__ out) {
    int idx = blockIdx.x * blockDim.x + threadIdx.x;  // over B*K*C/4 float4s
    int c4 = idx & (CDIM / 4 - 1);
    int k  = (idx >> 7) & (KDIM - 1);
    int b  = idx >> 12;

    float4 s = make_float4(0.f, 0.f, 0.f, 0.f);
    float ws = 0.f;
#pragma unroll
    for (int ch = 0; ch < CHUNKS; ch++) {
        const float4* p = (const float4*)(g_wx +
            (size_t)(b * CHUNKS + ch) * KDIM * CDIM + k * CDIM) + c4;
        float4 v = *p;
        s.x += v.x; s.y += v.y; s.z += v.z; s.w += v.w;
        ws  += g_wsum[(b * CHUNKS + ch) * KDIM + k];
    }
    float4 cv = *((const float4*)(cw + k * CDIM) + c4);
    float4 o;
    o.x = s.x - ws * cv.x;
    o.y = s.y - ws * cv.y;
    o.z = s.z - ws * cv.z;
    o.w = s.w - ws * cv.w;
    *((float4*)out + idx) = o;
}

extern "C" void kernel_launch(void* const* d_in, const int* in_sizes, int n_in,
                              void* d_out, int out_size) {
    const float* x     = (const float*)d_in[0];
    const float* cw    = (const float*)d_in[1];
    const float* scale = (const float*)d_in[2];
    float* out = (float*)d_out;

    enc_main_kernel<<<BDIM * CHUNKS, 256>>>(x, cw, scale);
    enc_epilogue_kernel<<<(BDIM * KDIM * CDIM / 4) / 256, 256>>>(cw, out);
}